// round 8
// baseline (speedup 1.0000x reference)
#include <cuda_runtime.h>
#include <cuda_fp16.h>
#include <cstdint>

#define Bsz 8
#define Cch 64
#define Hh  128
#define Wwi 128
#define Och 64
#define HW  (Hh*Wwi)

#define THREADS 256
#define NTILES  (Bsz*Hh)        // 1024 blocks, 1 tile each
#define NSTEPS  64              // channel-major: one channel per MMA step (K padded 9->16)
#define NCHUNK  4               // 16 channels per chunk

// smem (floats): two chunk buffers [x: 16ch x (3*132, stride 400) | gc: 16 x 136]
#define XSTR    400
#define XGC_OFF 6400            // 16*400
#define GCSTR   136
#define BUF_FL  (XGC_OFF + 16*GCSTR)   // 8576
#define SMEM_FL (2*BUF_FL)             // 17152 fl = 68608 B

#define X_ELEMS 6336            // 16*3*132

// B fragments, channel-major: [c=64][lane=32][4 x uint4]  (uint4 j covers nt {2j,2j+1})
__device__ uint4 d_bfrag[NSTEPS*32*4];

// ---------------- helpers ----------------
__device__ __forceinline__ uint32_t smem_u32(const void* p) {
    uint32_t a;
    asm("{ .reg .u64 t; cvta.to.shared.u64 t, %1; cvt.u32.u64 %0, t; }"
        : "=r"(a) : "l"(p));
    return a;
}
__device__ __forceinline__ float tanh_fast(float v) {
    float y; asm("tanh.approx.f32 %0, %1;" : "=f"(y) : "f"(v)); return y;
}
__device__ __forceinline__ void cp4(uint32_t dst, const void* src, int nbytes) {
    asm volatile("cp.async.ca.shared.global [%0], [%1], 4, %2;"
                 :: "r"(dst), "l"(src), "r"(nbytes));
}
__device__ __forceinline__ void cp_commit() { asm volatile("cp.async.commit_group;"); }
__device__ __forceinline__ void cp_wait1()  { asm volatile("cp.async.wait_group 1;" ::: "memory"); }
__device__ __forceinline__ void cp_wait0()  { asm volatile("cp.async.wait_group 0;" ::: "memory"); }
__device__ __forceinline__ uint32_t packh2(float lo, float hi) {
    __half2 h = __floats2half2_rn(lo, hi);
    return *reinterpret_cast<uint32_t*>(&h);
}
__device__ __forceinline__ void hmma(float& c0, float& c1, float& c2, float& c3,
                                     uint32_t a0, uint32_t a1, uint32_t a2, uint32_t a3,
                                     uint32_t b0, uint32_t b1) {
    asm("mma.sync.aligned.m16n8k16.row.col.f32.f16.f16.f32 "
        "{%0,%1,%2,%3}, {%4,%5,%6,%7}, {%8,%9}, {%0,%1,%2,%3};"
        : "+f"(c0), "+f"(c1), "+f"(c2), "+f"(c3)
        : "r"(a0), "r"(a1), "r"(a2), "r"(a3), "r"(b0), "r"(b1));
}

// ---------------- B fragment prep (channel-major, slots>=9 are zero) ----------
__global__ void prep_bfrag(const float* __restrict__ w) {
    int i = blockIdx.x * blockDim.x + threadIdx.x;   // [c][lane][j]
    if (i < NSTEPS*32*4) {
        int j    = i & 3;
        int lane = (i >> 2) & 31;
        int c    = i >> 7;
        int kb   = (lane & 3) * 2;
        uint32_t v[4];
        #pragma unroll
        for (int t = 0; t < 2; ++t) {
            int nt = 2*j + t;
            int o  = nt*8 + (lane >> 2);
            float f[4];
            #pragma unroll
            for (int q = 0; q < 4; ++q) {
                int s = kb + (q >> 1)*8 + (q & 1);   // kb, kb+1, kb+8, kb+9
                f[q] = (s < 9) ? w[(o*Cch + c)*9 + s] : 0.f;
            }
            v[2*t]   = packh2(f[0], f[1]);
            v[2*t+1] = packh2(f[2], f[3]);
        }
        uint4 r; r.x = v[0]; r.y = v[1]; r.z = v[2]; r.w = v[3];
        d_bfrag[i] = r;
    }
}

// ---------------- main kernel ----------------
extern __shared__ float sm[];

__global__ void __launch_bounds__(THREADS, 2)
paka_hmma(const float* __restrict__ x,
          const float* __restrict__ gc,
          const float* __restrict__ gsp,
          float* __restrict__ out)
{
    const int tid  = threadIdx.x;
    const int lane = tid & 31;
    const int wid  = tid >> 5;
    const int t    = blockIdx.x;
    const int b    = t >> 7;
    const int h    = t & 127;

    const uint32_t sbase = smem_u32(sm);

    // ---- stage chunk 0 ----
    const float* xB  = x  + (size_t)b*Cch*HW;
    const float* gcB = gc + (size_t)b*Cch*HW + (size_t)h*Wwi;
    auto stage_chunk = [&](int cg) {
        const uint32_t dst = sbase + (cg & 1)*BUF_FL*4;
        const float* xc = xB + (size_t)cg*16*HW;
        #pragma unroll
        for (int it = 0; it < 25; ++it) {
            int idx = tid + it*THREADS;
            if (idx < X_ELEMS) {
                int r   = (int)(((unsigned)idx * 31776u) >> 22);   // idx/132
                int col = idx - r*132;
                int cl  = (r*86) >> 8;                             // r/3
                int di  = r - 3*cl;
                int gh  = h - 1 + di;
                int gw  = col - 1;
                bool inb = ((unsigned)gh < Hh) & ((unsigned)gw < Wwi);
                const float* src = inb ? (xc + (size_t)cl*HW + gh*Wwi + gw) : xB;
                cp4(dst + (uint32_t)(cl*XSTR + di*132 + col)*4, src, inb ? 4 : 0);
            }
        }
        const float* gcc = gcB + (size_t)cg*16*HW;
        #pragma unroll
        for (int it = 0; it < 8; ++it) {
            int idx = tid + it*THREADS;
            int cl = idx >> 7, w = idx & 127;
            cp4(dst + (uint32_t)(XGC_OFF + cl*GCSTR + w)*4, gcc + (size_t)cl*HW + w, 4);
        }
    };
    stage_chunk(0);
    cp_commit();

    const int r0 = wid*16 + (lane >> 2);
    const int r1 = r0 + 8;
    const int qp = (lane & 3)*2;

    // per-thread kk constants: kkA=qp, kkB=qp+1, kkC=8
    const int diA = qp / 3,        djA = qp - 3*diA;
    const int diB = (qp+1) / 3,    djB = (qp+1) - 3*diB;
    const int offA = diA*132 + djA;
    const int offB = diB*132 + djB;
    const int offC = 2*132 + 2;                 // kk=8

    // gs values for this thread's kk set, loaded once from gmem
    const float* gsb = gsp + (size_t)b*9*HW + (size_t)h*Wwi;
    const float gsA0 = __ldg(gsb + (size_t)qp*HW     + r0);
    const float gsA1 = __ldg(gsb + (size_t)qp*HW     + r1);
    const float gsB0 = __ldg(gsb + (size_t)(qp+1)*HW + r0);
    const float gsB1 = __ldg(gsb + (size_t)(qp+1)*HW + r1);
    const float gsC0 = __ldg(gsb + (size_t)8*HW      + r0);
    const float gsC1 = __ldg(gsb + (size_t)8*HW      + r1);

    float acc[32];
    #pragma unroll
    for (int i = 0; i < 32; ++i) acc[i] = 0.f;

    for (int cg = 0; cg < NCHUNK; ++cg) {
        if (cg + 1 < NCHUNK) { stage_chunk(cg + 1); cp_commit(); cp_wait1(); }
        else                 { cp_wait0(); }
        __syncthreads();

        const float* bs = sm + (cg & 1)*BUF_FL;
        const float* pA0 = bs + offA + r0;
        const float* pA1 = bs + offA + r1;
        const float* pB0 = bs + offB + r0;
        const float* pB1 = bs + offB + r1;
        const float* pC0 = bs + offC + r0;
        const float* pC1 = bs + offC + r1;
        const float* pg0 = bs + XGC_OFF + r0;
        const float* pg1 = bs + XGC_OFF + r1;

        #pragma unroll
        for (int cc = 0; cc < 16; ++cc) {
            const int c = cg*16 + cc;

            const uint4* bp = d_bfrag + ((size_t)c*32 + lane)*4;
            uint4 B0 = bp[0];
            uint4 B1 = bp[1];

            const float xA0 = pA0[cc*XSTR], xA1 = pA1[cc*XSTR];
            const float xB0 = pB0[cc*XSTR], xB1 = pB1[cc*XSTR];
            const float xC0 = pC0[cc*XSTR], xC1 = pC1[cc*XSTR];
            const float g0  = pg0[cc*GCSTR], g1 = pg1[cc*GCSTR];

            const float tA0 = tanh_fast(g0 + gsA0);
            const float tA1 = tanh_fast(g1 + gsA1);
            const float tB0 = tanh_fast(g0 + gsB0);
            const float tB1 = tanh_fast(g1 + gsB1);
            const float tC0 = tanh_fast(g0 + gsC0);
            const float tC1 = tanh_fast(g1 + gsC1);

            const float aA0 = fmaf(xA0, tA0, xA0);
            const float aA1 = fmaf(xA1, tA1, xA1);
            const float aB0 = fmaf(xB0, tB0, xB0);
            const float aB1 = fmaf(xB1, tB1, xB1);
            const float aC0 = fmaf(xC0, tC0, xC0);
            const float aC1 = fmaf(xC1, tC1, xC1);

            const uint32_t a0 = packh2(aA0, aB0);
            const uint32_t a1 = packh2(aA1, aB1);
            const uint32_t a2 = packh2(aC0, aC0);   // second half hits B=0
            const uint32_t a3 = packh2(aC1, aC1);

            hmma(acc[0],  acc[1],  acc[2],  acc[3],  a0,a1,a2,a3, B0.x, B0.y);
            hmma(acc[4],  acc[5],  acc[6],  acc[7],  a0,a1,a2,a3, B0.z, B0.w);
            hmma(acc[8],  acc[9],  acc[10], acc[11], a0,a1,a2,a3, B1.x, B1.y);
            hmma(acc[12], acc[13], acc[14], acc[15], a0,a1,a2,a3, B1.z, B1.w);

            uint4 B2 = bp[2];
            uint4 B3 = bp[3];
            hmma(acc[16], acc[17], acc[18], acc[19], a0,a1,a2,a3, B2.x, B2.y);
            hmma(acc[20], acc[21], acc[22], acc[23], a0,a1,a2,a3, B2.z, B2.w);
            hmma(acc[24], acc[25], acc[26], acc[27], a0,a1,a2,a3, B3.x, B3.y);
            hmma(acc[28], acc[29], acc[30], acc[31], a0,a1,a2,a3, B3.z, B3.w);
        }
        __syncthreads();   // all done reading bs before restaging
    }

    // ---- epilogue: D fragments -> out[b][o][h][w] ----
    float* ob = out + ((size_t)b*Och)*HW + (size_t)h*Wwi;
    #pragma unroll
    for (int nt = 0; nt < 8; ++nt) {
        const int o0 = nt*8 + qp;
        float* p = ob + (size_t)o0*HW;
        p[r0]      = acc[nt*4 + 0];
        p[HW + r0] = acc[nt*4 + 1];
        p[r1]      = acc[nt*4 + 2];
        p[HW + r1] = acc[nt*4 + 3];
    }
}

extern "C" void kernel_launch(void* const* d_in, const int* in_sizes, int n_in,
                              void* d_out, int out_size) {
    const float* x  = (const float*)d_in[0];
    const float* gc = (const float*)d_in[1];
    const float* gs = (const float*)d_in[2];
    const float* w  = (const float*)d_in[3];
    float* out = (float*)d_out;

    prep_bfrag<<<(NSTEPS*32*4 + 255)/256, 256>>>(w);

    const int smem_bytes = SMEM_FL * (int)sizeof(float);
    (void)cudaFuncSetAttribute(paka_hmma,
                               cudaFuncAttributeMaxDynamicSharedMemorySize,
                               smem_bytes);
    paka_hmma<<<NTILES, THREADS, smem_bytes>>>(x, gc, gs, out);
}

// round 9
// speedup vs baseline: 1.8523x; 1.8523x over previous
#include <cuda_runtime.h>
#include <cuda_fp16.h>
#include <cstdint>

#define Bsz 8
#define Cch 64
#define Hh  128
#define Wwi 128
#define Och 64
#define HW  (Hh*Wwi)

#define THREADS 256
#define NTILES  (Bsz*Hh)        // 1024 blocks, 1 tile each
#define NSTEPS  64              // channel-major: one channel per MMA step (K padded 9->16)
#define NCHUNK  4               // 16 channels per chunk

// smem (floats): two chunk buffers [x: 16ch x (3*132, stride 400) | gc: 16 x 136]
#define XSTR    400
#define XGC_OFF 6400            // 16*400
#define GCSTR   136
#define BUF_FL  (XGC_OFF + 16*GCSTR)   // 8576
#define SMEM_FL (2*BUF_FL)             // 17152 fl = 68608 B

#define X_ELEMS 6336            // 16*3*132

// B fragments, channel-major, WARP-COALESCED: [c=64][j=4][lane=32] x uint4
// (j covers nt {2j, 2j+1}; lane is innermost so a warp's LDG.128 is 512B contiguous)
__device__ uint4 d_bfrag[NSTEPS*4*32];

// ---------------- helpers ----------------
__device__ __forceinline__ uint32_t smem_u32(const void* p) {
    uint32_t a;
    asm("{ .reg .u64 t; cvta.to.shared.u64 t, %1; cvt.u32.u64 %0, t; }"
        : "=r"(a) : "l"(p));
    return a;
}
__device__ __forceinline__ float tanh_fast(float v) {
    float y; asm("tanh.approx.f32 %0, %1;" : "=f"(y) : "f"(v)); return y;
}
__device__ __forceinline__ void cp4(uint32_t dst, const void* src, int nbytes) {
    asm volatile("cp.async.ca.shared.global [%0], [%1], 4, %2;"
                 :: "r"(dst), "l"(src), "r"(nbytes));
}
__device__ __forceinline__ void cp_commit() { asm volatile("cp.async.commit_group;"); }
__device__ __forceinline__ void cp_wait1()  { asm volatile("cp.async.wait_group 1;" ::: "memory"); }
__device__ __forceinline__ void cp_wait0()  { asm volatile("cp.async.wait_group 0;" ::: "memory"); }
__device__ __forceinline__ uint32_t packh2(float lo, float hi) {
    __half2 h = __floats2half2_rn(lo, hi);
    return *reinterpret_cast<uint32_t*>(&h);
}
__device__ __forceinline__ void hmma(float& c0, float& c1, float& c2, float& c3,
                                     uint32_t a0, uint32_t a1, uint32_t a2, uint32_t a3,
                                     uint32_t b0, uint32_t b1) {
    asm("mma.sync.aligned.m16n8k16.row.col.f32.f16.f16.f32 "
        "{%0,%1,%2,%3}, {%4,%5,%6,%7}, {%8,%9}, {%0,%1,%2,%3};"
        : "+f"(c0), "+f"(c1), "+f"(c2), "+f"(c3)
        : "r"(a0), "r"(a1), "r"(a2), "r"(a3), "r"(b0), "r"(b1));
}

// ---------------- B fragment prep (channel-major, coalesced [c][j][lane]) ----
__global__ void prep_bfrag(const float* __restrict__ w) {
    int i = blockIdx.x * blockDim.x + threadIdx.x;   // [c][j][lane]
    if (i < NSTEPS*4*32) {
        int lane = i & 31;
        int j    = (i >> 5) & 3;
        int c    = i >> 7;
        int kb   = (lane & 3) * 2;
        uint32_t v[4];
        #pragma unroll
        for (int t = 0; t < 2; ++t) {
            int nt = 2*j + t;
            int o  = nt*8 + (lane >> 2);
            float f[4];
            #pragma unroll
            for (int q = 0; q < 4; ++q) {
                int s = kb + (q >> 1)*8 + (q & 1);   // kb, kb+1, kb+8, kb+9
                f[q] = (s < 9) ? w[(o*Cch + c)*9 + s] : 0.f;
            }
            v[2*t]   = packh2(f[0], f[1]);
            v[2*t+1] = packh2(f[2], f[3]);
        }
        uint4 r; r.x = v[0]; r.y = v[1]; r.z = v[2]; r.w = v[3];
        d_bfrag[i] = r;
    }
}

// ---------------- main kernel ----------------
extern __shared__ float sm[];

__global__ void __launch_bounds__(THREADS, 2)
paka_hmma(const float* __restrict__ x,
          const float* __restrict__ gc,
          const float* __restrict__ gsp,
          float* __restrict__ out)
{
    const int tid  = threadIdx.x;
    const int lane = tid & 31;
    const int wid  = tid >> 5;
    const int t    = blockIdx.x;
    const int b    = t >> 7;
    const int h    = t & 127;

    const uint32_t sbase = smem_u32(sm);

    // ---- stage chunk 0 ----
    const float* xB  = x  + (size_t)b*Cch*HW;
    const float* gcB = gc + (size_t)b*Cch*HW + (size_t)h*Wwi;
    auto stage_chunk = [&](int cg) {
        const uint32_t dst = sbase + (cg & 1)*BUF_FL*4;
        const float* xc = xB + (size_t)cg*16*HW;
        #pragma unroll
        for (int it = 0; it < 25; ++it) {
            int idx = tid + it*THREADS;
            if (idx < X_ELEMS) {
                int r   = (int)(((unsigned)idx * 31776u) >> 22);   // idx/132
                int col = idx - r*132;
                int cl  = (r*86) >> 8;                             // r/3
                int di  = r - 3*cl;
                int gh  = h - 1 + di;
                int gw  = col - 1;
                bool inb = ((unsigned)gh < Hh) & ((unsigned)gw < Wwi);
                const float* src = inb ? (xc + (size_t)cl*HW + gh*Wwi + gw) : xB;
                cp4(dst + (uint32_t)(cl*XSTR + di*132 + col)*4, src, inb ? 4 : 0);
            }
        }
        const float* gcc = gcB + (size_t)cg*16*HW;
        #pragma unroll
        for (int it = 0; it < 8; ++it) {
            int idx = tid + it*THREADS;
            int cl = idx >> 7, w = idx & 127;
            cp4(dst + (uint32_t)(XGC_OFF + cl*GCSTR + w)*4, gcc + (size_t)cl*HW + w, 4);
        }
    };
    stage_chunk(0);
    cp_commit();

    const int r0 = wid*16 + (lane >> 2);
    const int r1 = r0 + 8;
    const int qp = (lane & 3)*2;

    // per-thread kk constants: kkA=qp, kkB=qp+1, kkC=8
    const int diA = qp / 3,        djA = qp - 3*diA;
    const int diB = (qp+1) / 3,    djB = (qp+1) - 3*diB;
    const int offA = diA*132 + djA;
    const int offB = diB*132 + djB;
    const int offC = 2*132 + 2;                 // kk=8

    // gs values for this thread's kk set, loaded once from gmem
    const float* gsb = gsp + (size_t)b*9*HW + (size_t)h*Wwi;
    const float gsA0 = __ldg(gsb + (size_t)qp*HW     + r0);
    const float gsA1 = __ldg(gsb + (size_t)qp*HW     + r1);
    const float gsB0 = __ldg(gsb + (size_t)(qp+1)*HW + r0);
    const float gsB1 = __ldg(gsb + (size_t)(qp+1)*HW + r1);
    const float gsC0 = __ldg(gsb + (size_t)8*HW      + r0);
    const float gsC1 = __ldg(gsb + (size_t)8*HW      + r1);

    float acc[32];
    #pragma unroll
    for (int i = 0; i < 32; ++i) acc[i] = 0.f;

    for (int cg = 0; cg < NCHUNK; ++cg) {
        if (cg + 1 < NCHUNK) { stage_chunk(cg + 1); cp_commit(); cp_wait1(); }
        else                 { cp_wait0(); }
        __syncthreads();

        const float* bs = sm + (cg & 1)*BUF_FL;
        const float* pA0 = bs + offA + r0;
        const float* pA1 = bs + offA + r1;
        const float* pB0 = bs + offB + r0;
        const float* pB1 = bs + offB + r1;
        const float* pC0 = bs + offC + r0;
        const float* pC1 = bs + offC + r1;
        const float* pg0 = bs + XGC_OFF + r0;
        const float* pg1 = bs + XGC_OFF + r1;

        #pragma unroll
        for (int cc = 0; cc < 16; ++cc) {
            const int c = cg*16 + cc;

            // coalesced: warp reads 512B contiguous per load (4 wavefronts)
            const uint4* bp = d_bfrag + (size_t)c*128 + lane;
            uint4 B0 = bp[0];
            uint4 B1 = bp[32];

            const float xA0 = pA0[cc*XSTR], xA1 = pA1[cc*XSTR];
            const float xB0 = pB0[cc*XSTR], xB1 = pB1[cc*XSTR];
            const float xC0 = pC0[cc*XSTR], xC1 = pC1[cc*XSTR];
            const float g0  = pg0[cc*GCSTR], g1 = pg1[cc*GCSTR];

            const float tA0 = tanh_fast(g0 + gsA0);
            const float tA1 = tanh_fast(g1 + gsA1);
            const float tB0 = tanh_fast(g0 + gsB0);
            const float tB1 = tanh_fast(g1 + gsB1);
            const float tC0 = tanh_fast(g0 + gsC0);
            const float tC1 = tanh_fast(g1 + gsC1);

            const float aA0 = fmaf(xA0, tA0, xA0);
            const float aA1 = fmaf(xA1, tA1, xA1);
            const float aB0 = fmaf(xB0, tB0, xB0);
            const float aB1 = fmaf(xB1, tB1, xB1);
            const float aC0 = fmaf(xC0, tC0, xC0);
            const float aC1 = fmaf(xC1, tC1, xC1);

            const uint32_t a0 = packh2(aA0, aB0);
            const uint32_t a1 = packh2(aA1, aB1);
            const uint32_t a2 = packh2(aC0, aC0);   // second half hits B=0
            const uint32_t a3 = packh2(aC1, aC1);

            hmma(acc[0],  acc[1],  acc[2],  acc[3],  a0,a1,a2,a3, B0.x, B0.y);
            hmma(acc[4],  acc[5],  acc[6],  acc[7],  a0,a1,a2,a3, B0.z, B0.w);
            hmma(acc[8],  acc[9],  acc[10], acc[11], a0,a1,a2,a3, B1.x, B1.y);
            hmma(acc[12], acc[13], acc[14], acc[15], a0,a1,a2,a3, B1.z, B1.w);

            uint4 B2 = bp[64];
            uint4 B3 = bp[96];
            hmma(acc[16], acc[17], acc[18], acc[19], a0,a1,a2,a3, B2.x, B2.y);
            hmma(acc[20], acc[21], acc[22], acc[23], a0,a1,a2,a3, B2.z, B2.w);
            hmma(acc[24], acc[25], acc[26], acc[27], a0,a1,a2,a3, B3.x, B3.y);
            hmma(acc[28], acc[29], acc[30], acc[31], a0,a1,a2,a3, B3.z, B3.w);
        }
        __syncthreads();   // all done reading bs before restaging
    }

    // ---- epilogue: D fragments -> out[b][o][h][w] ----
    float* ob = out + ((size_t)b*Och)*HW + (size_t)h*Wwi;
    #pragma unroll
    for (int nt = 0; nt < 8; ++nt) {
        const int o0 = nt*8 + qp;
        float* p = ob + (size_t)o0*HW;
        p[r0]      = acc[nt*4 + 0];
        p[HW + r0] = acc[nt*4 + 1];
        p[r1]      = acc[nt*4 + 2];
        p[HW + r1] = acc[nt*4 + 3];
    }
}

extern "C" void kernel_launch(void* const* d_in, const int* in_sizes, int n_in,
                              void* d_out, int out_size) {
    const float* x  = (const float*)d_in[0];
    const float* gc = (const float*)d_in[1];
    const float* gs = (const float*)d_in[2];
    const float* w  = (const float*)d_in[3];
    float* out = (float*)d_out;

    prep_bfrag<<<(NSTEPS*4*32 + 255)/256, 256>>>(w);

    const int smem_bytes = SMEM_FL * (int)sizeof(float);
    (void)cudaFuncSetAttribute(paka_hmma,
                               cudaFuncAttributeMaxDynamicSharedMemorySize,
                               smem_bytes);
    paka_hmma<<<NTILES, THREADS, smem_bytes>>>(x, gc, gs, out);
}

// round 10
// speedup vs baseline: 2.4807x; 1.3392x over previous
#include <cuda_runtime.h>
#include <cuda_fp16.h>
#include <cstdint>

#define Bsz 8
#define Cch 64
#define Hh  128
#define Wwi 128
#define Och 64
#define HW  (Hh*Wwi)

#define THREADS 256
#define NTILES  (Bsz*Hh)        // 1024 blocks, 1 tile each
#define NSUPER  4               // super-groups of 16 channels
#define NPH     9               // phases (kernel positions) per super-group
#define NSTEPS  (NSUPER*NPH)    // 36 MMA steps, no padding

// smem (floats): two chunk buffers [x: 16ch x (3*132), stride 404 | gc: 16 x 132]
// strides chosen so 2*stride ≡ 8 (mod 32) -> qp-groups hit banks 0/8/16/24: conflict-free
#define XSTR    404
#define XGC_OFF (16*XSTR)              // 6464
#define GCSTR   132
#define BUF_FL  (XGC_OFF + 16*GCSTR)   // 8576
#define SMEM_FL (2*BUF_FL)             // 17152 fl = 68608 B

#define X_ELEMS (16*3*132)             // 6336

// B fragments: [step=36][j=4][lane=32] x uint4 — lane innermost (coalesced),
// step (g,p): slot s -> channel g*16+s at kernel position kk=p. No zero slots.
__device__ uint4 d_bfrag[NSTEPS*4*32];

// ---------------- helpers ----------------
__device__ __forceinline__ uint32_t smem_u32(const void* p) {
    uint32_t a;
    asm("{ .reg .u64 t; cvta.to.shared.u64 t, %1; cvt.u32.u64 %0, t; }"
        : "=r"(a) : "l"(p));
    return a;
}
__device__ __forceinline__ float tanh_fast(float v) {
    float y; asm("tanh.approx.f32 %0, %1;" : "=f"(y) : "f"(v)); return y;
}
__device__ __forceinline__ void cp4(uint32_t dst, const void* src, int nbytes) {
    asm volatile("cp.async.ca.shared.global [%0], [%1], 4, %2;"
                 :: "r"(dst), "l"(src), "r"(nbytes));
}
__device__ __forceinline__ void cp_commit() { asm volatile("cp.async.commit_group;"); }
__device__ __forceinline__ void cp_wait1()  { asm volatile("cp.async.wait_group 1;" ::: "memory"); }
__device__ __forceinline__ void cp_wait0()  { asm volatile("cp.async.wait_group 0;" ::: "memory"); }
__device__ __forceinline__ uint32_t packh2(float lo, float hi) {
    __half2 h = __floats2half2_rn(lo, hi);
    return *reinterpret_cast<uint32_t*>(&h);
}
__device__ __forceinline__ void hmma(float& c0, float& c1, float& c2, float& c3,
                                     uint32_t a0, uint32_t a1, uint32_t a2, uint32_t a3,
                                     uint32_t b0, uint32_t b1) {
    asm("mma.sync.aligned.m16n8k16.row.col.f32.f16.f16.f32 "
        "{%0,%1,%2,%3}, {%4,%5,%6,%7}, {%8,%9}, {%0,%1,%2,%3};"
        : "+f"(c0), "+f"(c1), "+f"(c2), "+f"(c3)
        : "r"(a0), "r"(a1), "r"(a2), "r"(a3), "r"(b0), "r"(b1));
}

// ---------------- B fragment prep: step (g,p), slot s -> w[o][g*16+s][p] ----
__global__ void prep_bfrag(const float* __restrict__ w) {
    int i = blockIdx.x * blockDim.x + threadIdx.x;   // [step][j][lane]
    if (i < NSTEPS*4*32) {
        int lane = i & 31;
        int j    = (i >> 5) & 3;
        int step = i >> 7;
        int g    = step / NPH;
        int p    = step - g*NPH;
        int kb   = (lane & 3) * 2;
        uint32_t v[4];
        #pragma unroll
        for (int t = 0; t < 2; ++t) {
            int nt = 2*j + t;
            int o  = nt*8 + (lane >> 2);
            float f[4];
            #pragma unroll
            for (int q = 0; q < 4; ++q) {
                int s = kb + (q >> 1)*8 + (q & 1);   // slots kb, kb+1, kb+8, kb+9
                int c = g*16 + s;
                f[q] = w[(o*Cch + c)*9 + p];
            }
            v[2*t]   = packh2(f[0], f[1]);
            v[2*t+1] = packh2(f[2], f[3]);
        }
        uint4 r; r.x = v[0]; r.y = v[1]; r.z = v[2]; r.w = v[3];
        d_bfrag[i] = r;
    }
}

// ---------------- main kernel ----------------
extern __shared__ float sm[];

__global__ void __launch_bounds__(THREADS, 2)
paka_hmma(const float* __restrict__ x,
          const float* __restrict__ gc,
          const float* __restrict__ gsp,
          float* __restrict__ out)
{
    const int tid  = threadIdx.x;
    const int lane = tid & 31;
    const int wid  = tid >> 5;
    const int t    = blockIdx.x;
    const int b    = t >> 7;
    const int h    = t & 127;

    const uint32_t sbase = smem_u32(sm);

    // ---- staging ----
    const float* xB  = x  + (size_t)b*Cch*HW;
    const float* gcB = gc + (size_t)b*Cch*HW + (size_t)h*Wwi;
    auto stage_chunk = [&](int cg) {
        const uint32_t dst = sbase + (cg & 1)*BUF_FL*4;
        const float* xc = xB + (size_t)cg*16*HW;
        #pragma unroll
        for (int it = 0; it < 25; ++it) {
            int idx = tid + it*THREADS;
            if (idx < X_ELEMS) {
                int r   = (int)(((unsigned)idx * 31776u) >> 22);   // idx/132
                int col = idx - r*132;
                int cl  = (r*86) >> 8;                             // r/3
                int di  = r - 3*cl;
                int gh  = h - 1 + di;
                int gw  = col - 1;
                bool inb = ((unsigned)gh < Hh) & ((unsigned)gw < Wwi);
                const float* src = inb ? (xc + (size_t)cl*HW + gh*Wwi + gw) : xB;
                cp4(dst + (uint32_t)(cl*XSTR + di*132 + col)*4, src, inb ? 4 : 0);
            }
        }
        const float* gcc = gcB + (size_t)cg*16*HW;
        #pragma unroll
        for (int it = 0; it < 8; ++it) {
            int idx = tid + it*THREADS;
            int cl = idx >> 7, w = idx & 127;
            cp4(dst + (uint32_t)(XGC_OFF + cl*GCSTR + w)*4, gcc + (size_t)cl*HW + w, 4);
        }
    };
    stage_chunk(0);
    cp_commit();

    const int r0 = wid*16 + (lane >> 2);
    const int r1 = r0 + 8;
    const int qp = (lane & 3)*2;

    // gs values for all 9 kernel positions at r0/r1, loaded once from gmem
    const float* gsb = gsp + (size_t)b*9*HW + (size_t)h*Wwi;
    float gs0[9], gs1[9];
    #pragma unroll
    for (int p = 0; p < 9; ++p) {
        gs0[p] = __ldg(gsb + (size_t)p*HW + r0);
        gs1[p] = __ldg(gsb + (size_t)p*HW + r1);
    }

    float acc[32];
    #pragma unroll
    for (int i = 0; i < 32; ++i) acc[i] = 0.f;

    for (int g = 0; g < NSUPER; ++g) {
        if (g + 1 < NSUPER) { stage_chunk(g + 1); cp_commit(); cp_wait1(); }
        else                { cp_wait0(); }
        __syncthreads();

        const float* bs = sm + (g & 1)*BUF_FL;
        // per-thread channel base pointers (channels qp, qp+1, qp+8, qp+9)
        const float* p00 = bs + (qp    )*XSTR + r0;   // j=0, row r0
        const float* p01 = bs + (qp    )*XSTR + r1;
        const float* p10 = bs + (qp + 1)*XSTR + r0;
        const float* p11 = bs + (qp + 1)*XSTR + r1;
        const float* p20 = bs + (qp + 8)*XSTR + r0;
        const float* p21 = bs + (qp + 8)*XSTR + r1;
        const float* p30 = bs + (qp + 9)*XSTR + r0;
        const float* p31 = bs + (qp + 9)*XSTR + r1;

        // gc values for this super-group's 4 channels x 2 rows (conflict-free LDS)
        const float* gp = bs + XGC_OFF;
        const float g00 = gp[(qp    )*GCSTR + r0], g01 = gp[(qp    )*GCSTR + r1];
        const float g10 = gp[(qp + 1)*GCSTR + r0], g11 = gp[(qp + 1)*GCSTR + r1];
        const float g20 = gp[(qp + 8)*GCSTR + r0], g21 = gp[(qp + 8)*GCSTR + r1];
        const float g30 = gp[(qp + 9)*GCSTR + r0], g31 = gp[(qp + 9)*GCSTR + r1];

        #pragma unroll
        for (int p = 0; p < NPH; ++p) {
            const int di  = p / 3;
            const int dj  = p - 3*di;
            const int imm = di*132 + dj;          // compile-time after unroll

            const uint4* bp = d_bfrag + (size_t)(g*NPH + p)*128 + lane;
            uint4 B0 = bp[0];
            uint4 B1 = bp[32];

            const float x00 = p00[imm], x01 = p01[imm];
            const float x10 = p10[imm], x11 = p11[imm];
            const float x20 = p20[imm], x21 = p21[imm];
            const float x30 = p30[imm], x31 = p31[imm];

            const float t00 = tanh_fast(g00 + gs0[p]);
            const float t01 = tanh_fast(g01 + gs1[p]);
            const float t10 = tanh_fast(g10 + gs0[p]);
            const float t11 = tanh_fast(g11 + gs1[p]);
            const float t20 = tanh_fast(g20 + gs0[p]);
            const float t21 = tanh_fast(g21 + gs1[p]);
            const float t30 = tanh_fast(g30 + gs0[p]);
            const float t31 = tanh_fast(g31 + gs1[p]);

            const uint32_t a0 = packh2(fmaf(x00, t00, x00), fmaf(x10, t10, x10));
            const uint32_t a1 = packh2(fmaf(x01, t01, x01), fmaf(x11, t11, x11));
            const uint32_t a2 = packh2(fmaf(x20, t20, x20), fmaf(x30, t30, x30));
            const uint32_t a3 = packh2(fmaf(x21, t21, x21), fmaf(x31, t31, x31));

            hmma(acc[0],  acc[1],  acc[2],  acc[3],  a0,a1,a2,a3, B0.x, B0.y);
            hmma(acc[4],  acc[5],  acc[6],  acc[7],  a0,a1,a2,a3, B0.z, B0.w);
            hmma(acc[8],  acc[9],  acc[10], acc[11], a0,a1,a2,a3, B1.x, B1.y);
            hmma(acc[12], acc[13], acc[14], acc[15], a0,a1,a2,a3, B1.z, B1.w);

            uint4 B2 = bp[64];
            uint4 B3 = bp[96];
            hmma(acc[16], acc[17], acc[18], acc[19], a0,a1,a2,a3, B2.x, B2.y);
            hmma(acc[20], acc[21], acc[22], acc[23], a0,a1,a2,a3, B2.z, B2.w);
            hmma(acc[24], acc[25], acc[26], acc[27], a0,a1,a2,a3, B3.x, B3.y);
            hmma(acc[28], acc[29], acc[30], acc[31], a0,a1,a2,a3, B3.z, B3.w);
        }
        __syncthreads();   // all done reading bs before restaging
    }

    // ---- epilogue: D fragments -> out[b][o][h][w] ----
    float* ob = out + ((size_t)b*Och)*HW + (size_t)h*Wwi;
    #pragma unroll
    for (int nt = 0; nt < 8; ++nt) {
        const int o0 = nt*8 + qp;
        float* p = ob + (size_t)o0*HW;
        p[r0]      = acc[nt*4 + 0];
        p[HW + r0] = acc[nt*4 + 1];
        p[r1]      = acc[nt*4 + 2];
        p[HW + r1] = acc[nt*4 + 3];
    }
}

extern "C" void kernel_launch(void* const* d_in, const int* in_sizes, int n_in,
                              void* d_out, int out_size) {
    const float* x  = (const float*)d_in[0];
    const float* gc = (const float*)d_in[1];
    const float* gs = (const float*)d_in[2];
    const float* w  = (const float*)d_in[3];
    float* out = (float*)d_out;

    prep_bfrag<<<(NSTEPS*4*32 + 255)/256, 256>>>(w);

    const int smem_bytes = SMEM_FL * (int)sizeof(float);
    (void)cudaFuncSetAttribute(paka_hmma,
                               cudaFuncAttributeMaxDynamicSharedMemorySize,
                               smem_bytes);
    paka_hmma<<<NTILES, THREADS, smem_bytes>>>(x, gc, gs, out);
}